// round 4
// baseline (speedup 1.0000x reference)
#include <cuda_runtime.h>
#include <cuda_bf16.h>

#define NN 100000
#define EE 1600000
#define DD 128

// Scratch (allocation-free rule: __device__ globals)
__device__ float g_h  [NN * DD];
__device__ float g_h2 [NN * DD];
__device__ float g_agg[NN * DD];
__device__ float g_deg[NN];
__device__ int   g_src[EE];
__device__ int   g_dst[EE];
__device__ int   g_is64;

// ---------------------------------------------------------------------------
// Detect edge_index element width. Samples the first EE int64 slots (safe for
// both layouts: int32 buffer holds 2*EE int32 = EE int64 slots).
__global__ void detect_kernel(const long long* __restrict__ ei) {
    if (blockIdx.x == 0 && threadIdx.x == 0) {
        int ok = 1;
        #pragma unroll
        for (int i = 0; i < 16; i++) {
            long long v = ei[(size_t)i * (EE / 16) + 3];
            if (v < 0 || v >= NN) ok = 0;
        }
        g_is64 = ok;
    }
}

// Materialize int32 src/dst under either dtype; accumulate degree once.
__global__ void convert_kernel(const void* __restrict__ ei_raw) {
    int e = blockIdx.x * blockDim.x + threadIdx.x;
    if (e >= EE) return;
    int s, d;
    if (g_is64) {
        const long long* ei = (const long long*)ei_raw;
        s = (int)ei[e];
        d = (int)ei[EE + e];
    } else {
        const int* ei = (const int*)ei_raw;
        s = ei[e];
        d = ei[EE + e];
    }
    g_src[e] = s;
    g_dst[e] = d;
    atomicAdd(&g_deg[d], 1.0f);
}

// ---------------------------------------------------------------------------
__global__ void zero_deg_kernel() {
    int i = blockIdx.x * blockDim.x + threadIdx.x;
    if (i < NN) g_deg[i] = 0.0f;
}

__global__ void zero_agg_kernel() {
    int idx = blockIdx.x * blockDim.x + threadIdx.x;
    int stride = gridDim.x * blockDim.x;
    float4 z = make_float4(0.f, 0.f, 0.f, 0.f);
    float4* p = reinterpret_cast<float4*>(g_agg);
    for (int i = idx; i < NN * DD / 4; i += stride) p[i] = z;
}

// ---------------------------------------------------------------------------
// Y = relu(X @ W^T + b), X:[n,128], W:[128,128] row-major (out,in), Y:[n,128]
// Block: 256 threads, BM=64 rows. Dyn smem: Wt[128][132] + Xs[64][132].
#define LIN_SMEM ((128 * 132 + 64 * 132) * 4)

__global__ void lin_relu_kernel(const float* __restrict__ X,
                                const float* __restrict__ W,
                                const float* __restrict__ b,
                                float* __restrict__ Y) {
    extern __shared__ float sm[];
    float* Wt = sm;               // [128][132], Wt[k][o] = W[o][k]
    float* Xs = sm + 128 * 132;   // [64][132]

    int tid = threadIdx.x;
    int rowBase = blockIdx.x * 64;

    for (int idx = tid; idx < 128 * 128; idx += 256) {
        int o = idx >> 7, k = idx & 127;
        Wt[k * 132 + o] = W[idx];
    }
    for (int idx = tid; idx < 64 * 32; idx += 256) {
        int r = idx >> 5, c4 = idx & 31;
        int row = rowBase + r;
        float4 v = make_float4(0.f, 0.f, 0.f, 0.f);
        if (row < NN)
            v = reinterpret_cast<const float4*>(X + (size_t)row * DD)[c4];
        *reinterpret_cast<float4*>(&Xs[r * 132 + c4 * 4]) = v;
    }
    __syncthreads();

    int ty = tid >> 4, tx = tid & 15;   // 16x16 thread tile
    float acc[4][8];
    #pragma unroll
    for (int i = 0; i < 4; i++)
        #pragma unroll
        for (int j = 0; j < 8; j++) acc[i][j] = 0.f;

    #pragma unroll 8
    for (int k = 0; k < 128; k++) {
        float xv[4];
        #pragma unroll
        for (int i = 0; i < 4; i++) xv[i] = Xs[(ty * 4 + i) * 132 + k];
        float4 w0 = *reinterpret_cast<const float4*>(&Wt[k * 132 + tx * 8]);
        float4 w1 = *reinterpret_cast<const float4*>(&Wt[k * 132 + tx * 8 + 4]);
        float wv[8] = {w0.x, w0.y, w0.z, w0.w, w1.x, w1.y, w1.z, w1.w};
        #pragma unroll
        for (int i = 0; i < 4; i++)
            #pragma unroll
            for (int j = 0; j < 8; j++) acc[i][j] += xv[i] * wv[j];
    }

    int col0 = tx * 8;
    float bb[8];
    #pragma unroll
    for (int j = 0; j < 8; j++) bb[j] = b[col0 + j];
    #pragma unroll
    for (int i = 0; i < 4; i++) {
        int row = rowBase + ty * 4 + i;
        if (row < NN) {
            float4 o0, o1;
            o0.x = fmaxf(acc[i][0] + bb[0], 0.f);
            o0.y = fmaxf(acc[i][1] + bb[1], 0.f);
            o0.z = fmaxf(acc[i][2] + bb[2], 0.f);
            o0.w = fmaxf(acc[i][3] + bb[3], 0.f);
            o1.x = fmaxf(acc[i][4] + bb[4], 0.f);
            o1.y = fmaxf(acc[i][5] + bb[5], 0.f);
            o1.z = fmaxf(acc[i][6] + bb[6], 0.f);
            o1.w = fmaxf(acc[i][7] + bb[7], 0.f);
            float4* yp = reinterpret_cast<float4*>(Y + (size_t)row * DD + col0);
            yp[0] = o0;
            yp[1] = o1;
        }
    }
}

// ---------------------------------------------------------------------------
// Edge scatter: agg[dst] += H[src]. One warp per edge, vector red (4 floats/lane).
__global__ void scatter_kernel(const float* __restrict__ H) {
    int warpId = (blockIdx.x * blockDim.x + threadIdx.x) >> 5;
    int lane = threadIdx.x & 31;
    if (warpId >= EE) return;
    int src = g_src[warpId];
    int dst = g_dst[warpId];
    float4 v = reinterpret_cast<const float4*>(H + (size_t)src * DD)[lane];
    float* a = g_agg + (size_t)dst * DD + lane * 4;
    asm volatile("red.global.add.v4.f32 [%0], {%1, %2, %3, %4};"
                 :: "l"(a), "f"(v.x), "f"(v.y), "f"(v.z), "f"(v.w)
                 : "memory");
}

// ---------------------------------------------------------------------------
// Y = relu( (agg/max(deg,1)) @ Wl^T + bl + H @ Wr^T )
// Dyn smem: Wt[256][132] (Wl rows 0..127, Wr rows 128..255) + Xs[64][132].
#define COMB_SMEM ((256 * 132 + 64 * 132) * 4)

__global__ void sage_combine_kernel(const float* __restrict__ H,
                                    const float* __restrict__ Wl,
                                    const float* __restrict__ bl,
                                    const float* __restrict__ Wr,
                                    float* __restrict__ Y) {
    extern __shared__ float sm[];
    float* Wt = sm;               // [256][132]
    float* Xs = sm + 256 * 132;   // [64][132]

    int tid = threadIdx.x;
    int rowBase = blockIdx.x * 64;

    for (int idx = tid; idx < 128 * 128; idx += 256) {
        int o = idx >> 7, k = idx & 127;
        Wt[k * 132 + o] = Wl[idx];
        Wt[(128 + k) * 132 + o] = Wr[idx];
    }
    // mean tile
    for (int idx = tid; idx < 64 * 32; idx += 256) {
        int r = idx >> 5, c4 = idx & 31;
        int row = rowBase + r;
        float4 v = make_float4(0.f, 0.f, 0.f, 0.f);
        if (row < NN) {
            v = reinterpret_cast<const float4*>(g_agg + (size_t)row * DD)[c4];
            float inv = 1.0f / fmaxf(g_deg[row], 1.0f);
            v.x *= inv; v.y *= inv; v.z *= inv; v.w *= inv;
        }
        *reinterpret_cast<float4*>(&Xs[r * 132 + c4 * 4]) = v;
    }
    __syncthreads();

    int ty = tid >> 4, tx = tid & 15;
    float acc[4][8];
    #pragma unroll
    for (int i = 0; i < 4; i++)
        #pragma unroll
        for (int j = 0; j < 8; j++) acc[i][j] = 0.f;

    // pass 1: mean @ Wl^T
    #pragma unroll 8
    for (int k = 0; k < 128; k++) {
        float xv[4];
        #pragma unroll
        for (int i = 0; i < 4; i++) xv[i] = Xs[(ty * 4 + i) * 132 + k];
        float4 w0 = *reinterpret_cast<const float4*>(&Wt[k * 132 + tx * 8]);
        float4 w1 = *reinterpret_cast<const float4*>(&Wt[k * 132 + tx * 8 + 4]);
        float wv[8] = {w0.x, w0.y, w0.z, w0.w, w1.x, w1.y, w1.z, w1.w};
        #pragma unroll
        for (int i = 0; i < 4; i++)
            #pragma unroll
            for (int j = 0; j < 8; j++) acc[i][j] += xv[i] * wv[j];
    }
    __syncthreads();

    // reload Xs with H tile
    for (int idx = tid; idx < 64 * 32; idx += 256) {
        int r = idx >> 5, c4 = idx & 31;
        int row = rowBase + r;
        float4 v = make_float4(0.f, 0.f, 0.f, 0.f);
        if (row < NN)
            v = reinterpret_cast<const float4*>(H + (size_t)row * DD)[c4];
        *reinterpret_cast<float4*>(&Xs[r * 132 + c4 * 4]) = v;
    }
    __syncthreads();

    // pass 2: H @ Wr^T
    #pragma unroll 8
    for (int k = 0; k < 128; k++) {
        float xv[4];
        #pragma unroll
        for (int i = 0; i < 4; i++) xv[i] = Xs[(ty * 4 + i) * 132 + k];
        float4 w0 = *reinterpret_cast<const float4*>(&Wt[(128 + k) * 132 + tx * 8]);
        float4 w1 = *reinterpret_cast<const float4*>(&Wt[(128 + k) * 132 + tx * 8 + 4]);
        float wv[8] = {w0.x, w0.y, w0.z, w0.w, w1.x, w1.y, w1.z, w1.w};
        #pragma unroll
        for (int i = 0; i < 4; i++)
            #pragma unroll
            for (int j = 0; j < 8; j++) acc[i][j] += xv[i] * wv[j];
    }

    int col0 = tx * 8;
    float bb[8];
    #pragma unroll
    for (int j = 0; j < 8; j++) bb[j] = bl[col0 + j];
    #pragma unroll
    for (int i = 0; i < 4; i++) {
        int row = rowBase + ty * 4 + i;
        if (row < NN) {
            float4 o0, o1;
            o0.x = fmaxf(acc[i][0] + bb[0], 0.f);
            o0.y = fmaxf(acc[i][1] + bb[1], 0.f);
            o0.z = fmaxf(acc[i][2] + bb[2], 0.f);
            o0.w = fmaxf(acc[i][3] + bb[3], 0.f);
            o1.x = fmaxf(acc[i][4] + bb[4], 0.f);
            o1.y = fmaxf(acc[i][5] + bb[5], 0.f);
            o1.z = fmaxf(acc[i][6] + bb[6], 0.f);
            o1.w = fmaxf(acc[i][7] + bb[7], 0.f);
            float4* yp = reinterpret_cast<float4*>(Y + (size_t)row * DD + col0);
            yp[0] = o0;
            yp[1] = o1;
        }
    }
}

// ---------------------------------------------------------------------------
extern "C" void kernel_launch(void* const* d_in, const int* in_sizes, int n_in,
                              void* d_out, int out_size) {
    const float* x     = (const float*)d_in[0];
    const void*  ei    = d_in[1];
    const float* W1    = (const float*)d_in[2];
    const float* b1    = (const float*)d_in[3];
    const float* W2    = (const float*)d_in[4];
    const float* b2    = (const float*)d_in[5];
    const float* c1_Wl = (const float*)d_in[6];
    const float* c1_bl = (const float*)d_in[7];
    const float* c1_Wr = (const float*)d_in[8];
    const float* c2_Wl = (const float*)d_in[9];
    const float* c2_bl = (const float*)d_in[10];
    const float* c2_Wr = (const float*)d_in[11];
    float* out = (float*)d_out;

    cudaFuncSetAttribute(lin_relu_kernel,
                         cudaFuncAttributeMaxDynamicSharedMemorySize, LIN_SMEM);
    cudaFuncSetAttribute(sage_combine_kernel,
                         cudaFuncAttributeMaxDynamicSharedMemorySize, COMB_SMEM);

    float *p_h, *p_h2;
    cudaGetSymbolAddress((void**)&p_h, g_h);
    cudaGetSymbolAddress((void**)&p_h2, g_h2);

    int nb = (NN + 63) / 64;                      // 1563 row-tiles
    int scatter_blocks = (EE * 32 + 255) / 256;   // one warp per edge
    int conv_blocks = (EE + 255) / 256;

    // edge preprocessing (deterministic, recomputed every call)
    detect_kernel<<<1, 32>>>((const long long*)ei);
    zero_deg_kernel<<<(NN + 255) / 256, 256>>>();
    convert_kernel<<<conv_blocks, 256>>>(ei);

    // layer 1: h = relu(x W1^T + b1)
    lin_relu_kernel<<<nb, 256, LIN_SMEM>>>(x, W1, b1, p_h);
    // sage 1
    zero_agg_kernel<<<1024, 256>>>();
    scatter_kernel<<<scatter_blocks, 256>>>(p_h);
    sage_combine_kernel<<<nb, 256, COMB_SMEM>>>(p_h, c1_Wl, c1_bl, c1_Wr, p_h2);
    // layer 2: h = relu(h2 W2^T + b2)
    lin_relu_kernel<<<nb, 256, LIN_SMEM>>>(p_h2, W2, b2, p_h);
    // sage 2 -> out
    zero_agg_kernel<<<1024, 256>>>();
    scatter_kernel<<<scatter_blocks, 256>>>(p_h);
    sage_combine_kernel<<<nb, 256, COMB_SMEM>>>(p_h, c2_Wl, c2_bl, c2_Wr, out);
}

// round 5
// speedup vs baseline: 1.1971x; 1.1971x over previous
#include <cuda_runtime.h>
#include <cuda_bf16.h>

#define NN 100000
#define EE 1600000
#define DD 128

// Scratch (allocation-free rule: __device__ globals)
__device__ float g_h  [NN * DD];
__device__ float g_h2 [NN * DD];
__device__ float g_agg[NN * DD];
__device__ float g_deg[NN];
__device__ int   g_src[EE];
__device__ int   g_dst[EE];
__device__ int   g_is64;

// ---------------------------------------------------------------------------
// Detect edge_index element width. Samples the first EE int64 slots (safe for
// both layouts: int32 buffer holds 2*EE int32 = EE int64 slots).
__global__ void detect_kernel(const long long* __restrict__ ei) {
    if (blockIdx.x == 0 && threadIdx.x == 0) {
        int ok = 1;
        #pragma unroll
        for (int i = 0; i < 16; i++) {
            long long v = ei[(size_t)i * (EE / 16) + 3];
            if (v < 0 || v >= NN) ok = 0;
        }
        g_is64 = ok;
    }
}

// Materialize int32 src/dst under either dtype; accumulate degree once.
__global__ void convert_kernel(const void* __restrict__ ei_raw) {
    int e = blockIdx.x * blockDim.x + threadIdx.x;
    if (e >= EE) return;
    int s, d;
    if (g_is64) {
        const long long* ei = (const long long*)ei_raw;
        s = (int)ei[e];
        d = (int)ei[EE + e];
    } else {
        const int* ei = (const int*)ei_raw;
        s = ei[e];
        d = ei[EE + e];
    }
    g_src[e] = s;
    g_dst[e] = d;
    atomicAdd(&g_deg[d], 1.0f);
}

// ---------------------------------------------------------------------------
__global__ void zero_deg_kernel() {
    int i = blockIdx.x * blockDim.x + threadIdx.x;
    if (i < NN) g_deg[i] = 0.0f;
}

__global__ void zero_agg_kernel() {
    int idx = blockIdx.x * blockDim.x + threadIdx.x;
    int stride = gridDim.x * blockDim.x;
    float4 z = make_float4(0.f, 0.f, 0.f, 0.f);
    float4* p = reinterpret_cast<float4*>(g_agg);
    for (int i = idx; i < NN * DD / 4; i += stride) p[i] = z;
}

// ---------------------------------------------------------------------------
// GEMM helpers: 128x128 block tile, 256 threads, 8x8 register tile per thread.
// Smem layouts use padded stride 132 (keeps float4 alignment; loader STS has
// 4-way conflicts but is ~6% of mainloop cost).

#define PAD 132

// Y = relu(X @ W^T + b), X:[n,128], W:[128,128] row-major (out,in)
// Dyn smem: Wt[128][PAD] + XsT[128][PAD]  (both [k][*] layouts)
#define LIN_SMEM ((128 * PAD + 128 * PAD) * 4)

__global__ __launch_bounds__(256, 1)
void lin_relu_kernel(const float* __restrict__ X,
                     const float* __restrict__ W,
                     const float* __restrict__ b,
                     float* __restrict__ Y) {
    extern __shared__ float sm[];
    float* Wt  = sm;                // [128][PAD]: Wt[k][o] = W[o][k]
    float* XsT = sm + 128 * PAD;    // [128][PAD]: XsT[k][r] = X[rowBase+r][k]

    int tid = threadIdx.x;
    int rowBase = blockIdx.x * 128;

    // load W transposed (coalesced LDG, 4-way-conflict STS)
    for (int idx = tid; idx < 128 * 128; idx += 256) {
        int o = idx >> 7, k = idx & 127;
        Wt[k * PAD + o] = W[idx];
    }
    // load X tile transposed
    for (int idx = tid; idx < 128 * 128; idx += 256) {
        int c = idx & 127, r = idx >> 7;
        int row = rowBase + r;
        float v = (row < NN) ? X[(size_t)row * DD + c] : 0.0f;
        XsT[c * PAD + r] = v;
    }
    __syncthreads();

    int ty = tid >> 4, tx = tid & 15;   // 16x16 threads; 8 rows x 8 cols each
    int r0 = ty * 8, c0 = tx * 8;

    float acc[8][8];
    #pragma unroll
    for (int i = 0; i < 8; i++)
        #pragma unroll
        for (int j = 0; j < 8; j++) acc[i][j] = 0.f;

    #pragma unroll 4
    for (int k = 0; k < 128; k++) {
        float4 x0 = *reinterpret_cast<const float4*>(&XsT[k * PAD + r0]);
        float4 x1 = *reinterpret_cast<const float4*>(&XsT[k * PAD + r0 + 4]);
        float4 w0 = *reinterpret_cast<const float4*>(&Wt[k * PAD + c0]);
        float4 w1 = *reinterpret_cast<const float4*>(&Wt[k * PAD + c0 + 4]);
        float xv[8] = {x0.x, x0.y, x0.z, x0.w, x1.x, x1.y, x1.z, x1.w};
        float wv[8] = {w0.x, w0.y, w0.z, w0.w, w1.x, w1.y, w1.z, w1.w};
        #pragma unroll
        for (int i = 0; i < 8; i++)
            #pragma unroll
            for (int j = 0; j < 8; j++) acc[i][j] += xv[i] * wv[j];
    }

    float bb[8];
    #pragma unroll
    for (int j = 0; j < 8; j++) bb[j] = b[c0 + j];
    #pragma unroll
    for (int i = 0; i < 8; i++) {
        int row = rowBase + r0 + i;
        if (row < NN) {
            float4 o0, o1;
            o0.x = fmaxf(acc[i][0] + bb[0], 0.f);
            o0.y = fmaxf(acc[i][1] + bb[1], 0.f);
            o0.z = fmaxf(acc[i][2] + bb[2], 0.f);
            o0.w = fmaxf(acc[i][3] + bb[3], 0.f);
            o1.x = fmaxf(acc[i][4] + bb[4], 0.f);
            o1.y = fmaxf(acc[i][5] + bb[5], 0.f);
            o1.z = fmaxf(acc[i][6] + bb[6], 0.f);
            o1.w = fmaxf(acc[i][7] + bb[7], 0.f);
            float4* yp = reinterpret_cast<float4*>(Y + (size_t)row * DD + c0);
            yp[0] = o0;
            yp[1] = o1;
        }
    }
}

// ---------------------------------------------------------------------------
// Edge scatter: agg[dst] += H[src]. One warp per edge, vector red (4 floats/lane).
__global__ void scatter_kernel(const float* __restrict__ H) {
    int warpId = (blockIdx.x * blockDim.x + threadIdx.x) >> 5;
    int lane = threadIdx.x & 31;
    if (warpId >= EE) return;
    int src = g_src[warpId];
    int dst = g_dst[warpId];
    float4 v = reinterpret_cast<const float4*>(H + (size_t)src * DD)[lane];
    float* a = g_agg + (size_t)dst * DD + lane * 4;
    asm volatile("red.global.add.v4.f32 [%0], {%1, %2, %3, %4};"
                 :: "l"(a), "f"(v.x), "f"(v.y), "f"(v.z), "f"(v.w)
                 : "memory");
}

// ---------------------------------------------------------------------------
// Y = relu( (agg/max(deg,1)) @ Wl^T + bl + H @ Wr^T )
// Dyn smem: Wt[256][PAD] (Wl k-rows 0..127, Wr k-rows 128..255)
//         + XsT[128][PAD] + invs[128]
#define COMB_SMEM ((256 * PAD + 128 * PAD + 128) * 4)

__global__ __launch_bounds__(256, 1)
void sage_combine_kernel(const float* __restrict__ H,
                         const float* __restrict__ Wl,
                         const float* __restrict__ bl,
                         const float* __restrict__ Wr,
                         float* __restrict__ Y) {
    extern __shared__ float sm[];
    float* Wt   = sm;                        // [256][PAD]
    float* XsT  = sm + 256 * PAD;            // [128][PAD]
    float* invs = sm + 256 * PAD + 128 * PAD;// [128]

    int tid = threadIdx.x;
    int rowBase = blockIdx.x * 128;

    for (int idx = tid; idx < 128 * 128; idx += 256) {
        int o = idx >> 7, k = idx & 127;
        Wt[k * PAD + o] = Wl[idx];
        Wt[(128 + k) * PAD + o] = Wr[idx];
    }
    if (tid < 128) {
        int row = rowBase + tid;
        invs[tid] = (row < NN) ? 1.0f / fmaxf(g_deg[row], 1.0f) : 0.0f;
    }
    __syncthreads();

    // mean tile (transposed)
    for (int idx = tid; idx < 128 * 128; idx += 256) {
        int c = idx & 127, r = idx >> 7;
        int row = rowBase + r;
        float v = (row < NN) ? g_agg[(size_t)row * DD + c] * invs[r] : 0.0f;
        XsT[c * PAD + r] = v;
    }
    __syncthreads();

    int ty = tid >> 4, tx = tid & 15;
    int r0 = ty * 8, c0 = tx * 8;

    float acc[8][8];
    #pragma unroll
    for (int i = 0; i < 8; i++)
        #pragma unroll
        for (int j = 0; j < 8; j++) acc[i][j] = 0.f;

    // pass 1: mean @ Wl^T
    #pragma unroll 4
    for (int k = 0; k < 128; k++) {
        float4 x0 = *reinterpret_cast<const float4*>(&XsT[k * PAD + r0]);
        float4 x1 = *reinterpret_cast<const float4*>(&XsT[k * PAD + r0 + 4]);
        float4 w0 = *reinterpret_cast<const float4*>(&Wt[k * PAD + c0]);
        float4 w1 = *reinterpret_cast<const float4*>(&Wt[k * PAD + c0 + 4]);
        float xv[8] = {x0.x, x0.y, x0.z, x0.w, x1.x, x1.y, x1.z, x1.w};
        float wv[8] = {w0.x, w0.y, w0.z, w0.w, w1.x, w1.y, w1.z, w1.w};
        #pragma unroll
        for (int i = 0; i < 8; i++)
            #pragma unroll
            for (int j = 0; j < 8; j++) acc[i][j] += xv[i] * wv[j];
    }
    __syncthreads();

    // reload XsT with H tile (transposed)
    for (int idx = tid; idx < 128 * 128; idx += 256) {
        int c = idx & 127, r = idx >> 7;
        int row = rowBase + r;
        float v = (row < NN) ? H[(size_t)row * DD + c] : 0.0f;
        XsT[c * PAD + r] = v;
    }
    __syncthreads();

    // pass 2: H @ Wr^T
    #pragma unroll 4
    for (int k = 0; k < 128; k++) {
        float4 x0 = *reinterpret_cast<const float4*>(&XsT[k * PAD + r0]);
        float4 x1 = *reinterpret_cast<const float4*>(&XsT[k * PAD + r0 + 4]);
        float4 w0 = *reinterpret_cast<const float4*>(&Wt[(128 + k) * PAD + c0]);
        float4 w1 = *reinterpret_cast<const float4*>(&Wt[(128 + k) * PAD + c0 + 4]);
        float xv[8] = {x0.x, x0.y, x0.z, x0.w, x1.x, x1.y, x1.z, x1.w};
        float wv[8] = {w0.x, w0.y, w0.z, w0.w, w1.x, w1.y, w1.z, w1.w};
        #pragma unroll
        for (int i = 0; i < 8; i++)
            #pragma unroll
            for (int j = 0; j < 8; j++) acc[i][j] += xv[i] * wv[j];
    }

    float bb[8];
    #pragma unroll
    for (int j = 0; j < 8; j++) bb[j] = bl[c0 + j];
    #pragma unroll
    for (int i = 0; i < 8; i++) {
        int row = rowBase + r0 + i;
        if (row < NN) {
            float4 o0, o1;
            o0.x = fmaxf(acc[i][0] + bb[0], 0.f);
            o0.y = fmaxf(acc[i][1] + bb[1], 0.f);
            o0.z = fmaxf(acc[i][2] + bb[2], 0.f);
            o0.w = fmaxf(acc[i][3] + bb[3], 0.f);
            o1.x = fmaxf(acc[i][4] + bb[4], 0.f);
            o1.y = fmaxf(acc[i][5] + bb[5], 0.f);
            o1.z = fmaxf(acc[i][6] + bb[6], 0.f);
            o1.w = fmaxf(acc[i][7] + bb[7], 0.f);
            float4* yp = reinterpret_cast<float4*>(Y + (size_t)row * DD + c0);
            yp[0] = o0;
            yp[1] = o1;
        }
    }
}

// ---------------------------------------------------------------------------
extern "C" void kernel_launch(void* const* d_in, const int* in_sizes, int n_in,
                              void* d_out, int out_size) {
    const float* x     = (const float*)d_in[0];
    const void*  ei    = d_in[1];
    const float* W1    = (const float*)d_in[2];
    const float* b1    = (const float*)d_in[3];
    const float* W2    = (const float*)d_in[4];
    const float* b2    = (const float*)d_in[5];
    const float* c1_Wl = (const float*)d_in[6];
    const float* c1_bl = (const float*)d_in[7];
    const float* c1_Wr = (const float*)d_in[8];
    const float* c2_Wl = (const float*)d_in[9];
    const float* c2_bl = (const float*)d_in[10];
    const float* c2_Wr = (const float*)d_in[11];
    float* out = (float*)d_out;

    cudaFuncSetAttribute(lin_relu_kernel,
                         cudaFuncAttributeMaxDynamicSharedMemorySize, LIN_SMEM);
    cudaFuncSetAttribute(sage_combine_kernel,
                         cudaFuncAttributeMaxDynamicSharedMemorySize, COMB_SMEM);

    float *p_h, *p_h2;
    cudaGetSymbolAddress((void**)&p_h, g_h);
    cudaGetSymbolAddress((void**)&p_h2, g_h2);

    int nb = (NN + 127) / 128;                    // 782 row-tiles
    int scatter_blocks = (EE * 32 + 255) / 256;   // one warp per edge
    int conv_blocks = (EE + 255) / 256;

    // edge preprocessing (deterministic, recomputed every call)
    detect_kernel<<<1, 32>>>((const long long*)ei);
    zero_deg_kernel<<<(NN + 255) / 256, 256>>>();
    convert_kernel<<<conv_blocks, 256>>>(ei);

    // layer 1: h = relu(x W1^T + b1)
    lin_relu_kernel<<<nb, 256, LIN_SMEM>>>(x, W1, b1, p_h);
    // sage 1
    zero_agg_kernel<<<1024, 256>>>();
    scatter_kernel<<<scatter_blocks, 256>>>(p_h);
    sage_combine_kernel<<<nb, 256, COMB_SMEM>>>(p_h, c1_Wl, c1_bl, c1_Wr, p_h2);
    // layer 2: h = relu(h2 W2^T + b2)
    lin_relu_kernel<<<nb, 256, LIN_SMEM>>>(p_h2, W2, b2, p_h);
    // sage 2 -> out
    zero_agg_kernel<<<1024, 256>>>();
    scatter_kernel<<<scatter_blocks, 256>>>(p_h);
    sage_combine_kernel<<<nb, 256, COMB_SMEM>>>(p_h, c2_Wl, c2_bl, c2_Wr, out);
}

// round 7
// speedup vs baseline: 1.7929x; 1.4977x over previous
#include <cuda_runtime.h>
#include <cuda_bf16.h>
#include <cstdint>

#define NN 100000
#define EE 1600000
#define DD 128

// Scratch (allocation-free rule: __device__ globals)
__device__ float g_h  [NN * DD];
__device__ float g_h2 [NN * DD];
__device__ float g_agg[NN * DD];
__device__ float g_deg[NN];
__device__ int   g_src[EE];
__device__ int   g_dst[EE];
__device__ int   g_is64;

// ===========================================================================
// PTX helpers (sm_80-compatible only: ldmatrix + mma.sync; NO tcgen05 — the
// harness compiles PTX at target compute_103, which rejects 'a' features)
// ===========================================================================
__device__ __forceinline__ uint32_t smem_u32(const void* p) {
    uint32_t a;
    asm("{ .reg .u64 t; cvta.to.shared.u64 t, %1; cvt.u32.u64 %0, t; }"
        : "=r"(a) : "l"(p));
    return a;
}

__device__ __forceinline__ void ldsm_x4(uint32_t* r, uint32_t addr) {
    asm volatile("ldmatrix.sync.aligned.m8n8.x4.shared.b16 {%0,%1,%2,%3}, [%4];"
                 : "=r"(r[0]), "=r"(r[1]), "=r"(r[2]), "=r"(r[3]) : "r"(addr));
}
__device__ __forceinline__ void ldsm_x2(uint32_t* r, uint32_t addr) {
    asm volatile("ldmatrix.sync.aligned.m8n8.x2.shared.b16 {%0,%1}, [%2];"
                 : "=r"(r[0]), "=r"(r[1]) : "r"(addr));
}
__device__ __forceinline__ void mma16816(float* d, const uint32_t* a,
                                         const uint32_t* b) {
    asm volatile(
        "mma.sync.aligned.m16n8k16.row.col.f32.bf16.bf16.f32 "
        "{%0,%1,%2,%3}, {%4,%5,%6,%7}, {%8,%9}, {%0,%1,%2,%3};"
        : "+f"(d[0]), "+f"(d[1]), "+f"(d[2]), "+f"(d[3])
        : "r"(a[0]), "r"(a[1]), "r"(a[2]), "r"(a[3]), "r"(b[0]), "r"(b[1]));
}

// ===========================================================================
// Smem tile layout: bf16 [128][BSTRIDE], BSTRIDE=136 (272B rows -> ldmatrix
// rows land on 4-bank-strided addresses, conflict-free 8-lane groups).
// Regions: A_hi, A_lo, B_hi, B_lo (B = weight, K-major = W row-major).
// ===========================================================================
#define BSTRIDE 136
#define TILE_B  (128 * BSTRIDE * 2)   // 34816 bytes
#define R_A_HI  0
#define R_A_LO  (TILE_B)
#define R_B_HI  (2 * TILE_B)
#define R_B_LO  (3 * TILE_B)
#define GEMM_SMEM (4 * TILE_B)        // 139264
#define COMB_SMEM (GEMM_SMEM + 512)   // + invs[128]

// split fp32 pair -> bf16 hi/lo
__device__ __forceinline__ void cvt_store_pair(char* sm, int r, int c, float2 v) {
    __nv_bfloat16 h0 = __float2bfloat16(v.x);
    __nv_bfloat16 h1 = __float2bfloat16(v.y);
    __nv_bfloat16 l0 = __float2bfloat16(v.x - __bfloat162float(h0));
    __nv_bfloat16 l1 = __float2bfloat16(v.y - __bfloat162float(h1));
    uint32_t off = (uint32_t)(r * BSTRIDE + c) * 2;
    *reinterpret_cast<__nv_bfloat162*>(sm + R_A_HI + off) = __halves2bfloat162(h0, h1);
    *reinterpret_cast<__nv_bfloat162*>(sm + R_A_LO + off) = __halves2bfloat162(l0, l1);
}
__device__ __forceinline__ void cvt_store_pair_B(char* sm, int r, int c, float2 v) {
    __nv_bfloat16 h0 = __float2bfloat16(v.x);
    __nv_bfloat16 h1 = __float2bfloat16(v.y);
    __nv_bfloat16 l0 = __float2bfloat16(v.x - __bfloat162float(h0));
    __nv_bfloat16 l1 = __float2bfloat16(v.y - __bfloat162float(h1));
    uint32_t off = (uint32_t)(r * BSTRIDE + c) * 2;
    *reinterpret_cast<__nv_bfloat162*>(sm + R_B_HI + off) = __halves2bfloat162(h0, h1);
    *reinterpret_cast<__nv_bfloat162*>(sm + R_B_LO + off) = __halves2bfloat162(l0, l1);
}

// Mainloop: warp tile 32x64 (wr 0..3, wc 0..1), 3-term split, accumulate.
__device__ __forceinline__ void mma_tile(uint32_t sb, float acc[2][8][4],
                                         int wr, int wc, int l) {
    for (int k = 0; k < 8; k++) {
        uint32_t ah0[4], ah1[4], al0[4], al1[4];
        uint32_t arow0 = (uint32_t)(wr * 32 + (l & 15));
        uint32_t acolk = (uint32_t)(k * 16 + (l >> 4) * 8);
        uint32_t aoff0 = (arow0 * BSTRIDE + acolk) * 2;
        uint32_t aoff1 = ((arow0 + 16) * BSTRIDE + acolk) * 2;
        ldsm_x4(ah0, sb + R_A_HI + aoff0);
        ldsm_x4(ah1, sb + R_A_HI + aoff1);
        ldsm_x4(al0, sb + R_A_LO + aoff0);
        ldsm_x4(al1, sb + R_A_LO + aoff1);
        #pragma unroll
        for (int nf = 0; nf < 8; nf++) {
            uint32_t bh[2], bl_[2];
            uint32_t brow = (uint32_t)(wc * 64 + nf * 8 + (l & 7));
            uint32_t bcol = (uint32_t)(k * 16 + ((l >> 3) & 1) * 8);
            uint32_t boff = (brow * BSTRIDE + bcol) * 2;
            ldsm_x2(bh, sb + R_B_HI + boff);
            ldsm_x2(bl_, sb + R_B_LO + boff);
            mma16816(acc[0][nf], ah0, bh);
            mma16816(acc[1][nf], ah1, bh);
            mma16816(acc[0][nf], ah0, bl_);
            mma16816(acc[1][nf], ah1, bl_);
            mma16816(acc[0][nf], al0, bh);
            mma16816(acc[1][nf], al1, bh);
        }
    }
}

__device__ __forceinline__ void epilogue(float acc[2][8][4], const float* bias,
                                         float* Y, int rowBase, int wr, int wc,
                                         int l) {
    #pragma unroll
    for (int mf = 0; mf < 2; mf++) {
        #pragma unroll
        for (int nf = 0; nf < 8; nf++) {
            int col = wc * 64 + nf * 8 + (l & 3) * 2;
            float b0 = __ldg(bias + col), b1 = __ldg(bias + col + 1);
            int row0 = rowBase + wr * 32 + mf * 16 + (l >> 2);
            if (row0 < NN) {
                float2 v;
                v.x = fmaxf(acc[mf][nf][0] + b0, 0.f);
                v.y = fmaxf(acc[mf][nf][1] + b1, 0.f);
                *reinterpret_cast<float2*>(Y + (size_t)row0 * DD + col) = v;
            }
            int row1 = row0 + 8;
            if (row1 < NN) {
                float2 v;
                v.x = fmaxf(acc[mf][nf][2] + b0, 0.f);
                v.y = fmaxf(acc[mf][nf][3] + b1, 0.f);
                *reinterpret_cast<float2*>(Y + (size_t)row1 * DD + col) = v;
            }
        }
    }
}

// ===========================================================================
// Edge preprocessing
// ===========================================================================
__global__ void detect_kernel(const long long* __restrict__ ei) {
    if (blockIdx.x == 0 && threadIdx.x == 0) {
        int ok = 1;
        #pragma unroll
        for (int i = 0; i < 16; i++) {
            long long v = ei[(size_t)i * (EE / 16) + 3];
            if (v < 0 || v >= NN) ok = 0;
        }
        g_is64 = ok;
    }
}

__global__ void convert_kernel(const void* __restrict__ ei_raw) {
    int e = blockIdx.x * blockDim.x + threadIdx.x;
    if (e >= EE) return;
    int s, d;
    if (g_is64) {
        const long long* ei = (const long long*)ei_raw;
        s = (int)ei[e];
        d = (int)ei[EE + e];
    } else {
        const int* ei = (const int*)ei_raw;
        s = ei[e];
        d = ei[EE + e];
    }
    g_src[e] = s;
    g_dst[e] = d;
    atomicAdd(&g_deg[d], 1.0f);
}

__global__ void zero_deg_kernel() {
    int i = blockIdx.x * blockDim.x + threadIdx.x;
    if (i < NN) g_deg[i] = 0.0f;
}

__global__ void zero_agg_kernel() {
    int idx = blockIdx.x * blockDim.x + threadIdx.x;
    int stride = gridDim.x * blockDim.x;
    float4 z = make_float4(0.f, 0.f, 0.f, 0.f);
    float4* p = reinterpret_cast<float4*>(g_agg);
    for (int i = idx; i < NN * DD / 4; i += stride) p[i] = z;
}

// ===========================================================================
// Edge scatter: agg[dst] += H[src]. One warp per edge, vector red.
// ===========================================================================
__global__ void scatter_kernel(const float* __restrict__ H) {
    int warpId = (blockIdx.x * blockDim.x + threadIdx.x) >> 5;
    int lane = threadIdx.x & 31;
    if (warpId >= EE) return;
    int src = g_src[warpId];
    int dst = g_dst[warpId];
    float4 v = reinterpret_cast<const float4*>(H + (size_t)src * DD)[lane];
    float* a = g_agg + (size_t)dst * DD + lane * 4;
    asm volatile("red.global.add.v4.f32 [%0], {%1, %2, %3, %4};"
                 :: "l"(a), "f"(v.x), "f"(v.y), "f"(v.z), "f"(v.w)
                 : "memory");
}

// ===========================================================================
// GEMM 1: Y = relu(X @ W^T + b)
// ===========================================================================
__global__ __launch_bounds__(256, 1)
void gemm_lin_kernel(const float* __restrict__ X, const float* __restrict__ W,
                     const float* __restrict__ b, float* __restrict__ Y) {
    extern __shared__ char sm[];
    uint32_t sb = smem_u32(sm);
    int tid = threadIdx.x, wid = tid >> 5, l = tid & 31;
    int wr = wid >> 1, wc = wid & 1;
    int rowBase = blockIdx.x * 128;

    // W tile (B region) + X tile (A region)
    for (int idx = tid; idx < 128 * 64; idx += 256) {
        int r = idx >> 6, c = (idx & 63) * 2;
        float2 vw = *reinterpret_cast<const float2*>(W + r * 128 + c);
        cvt_store_pair_B(sm, r, c, vw);
        int row = rowBase + r;
        float2 vx = make_float2(0.f, 0.f);
        if (row < NN) vx = *reinterpret_cast<const float2*>(X + (size_t)row * DD + c);
        cvt_store_pair(sm, r, c, vx);
    }
    __syncthreads();

    float acc[2][8][4];
    #pragma unroll
    for (int i = 0; i < 2; i++)
        #pragma unroll
        for (int j = 0; j < 8; j++)
            #pragma unroll
            for (int q = 0; q < 4; q++) acc[i][j][q] = 0.f;

    mma_tile(sb, acc, wr, wc, l);
    epilogue(acc, b, Y, rowBase, wr, wc, l);
}

// ===========================================================================
// GEMM 2: Y = relu( mean @ Wl^T + bl + H @ Wr^T ), two phases, reg accum
// ===========================================================================
__global__ __launch_bounds__(256, 1)
void gemm_sage_kernel(const float* __restrict__ H, const float* __restrict__ Wl,
                      const float* __restrict__ bl, const float* __restrict__ Wr,
                      float* __restrict__ Y) {
    extern __shared__ char sm[];
    uint32_t sb = smem_u32(sm);
    float* invs = reinterpret_cast<float*>(sm + GEMM_SMEM);
    int tid = threadIdx.x, wid = tid >> 5, l = tid & 31;
    int wr = wid >> 1, wc = wid & 1;
    int rowBase = blockIdx.x * 128;

    if (tid < 128) {
        int row = rowBase + tid;
        invs[tid] = (row < NN) ? 1.0f / fmaxf(g_deg[row], 1.0f) : 0.0f;
    }
    __syncthreads();

    // phase 1 tiles: B = Wl, A = mean
    for (int idx = tid; idx < 128 * 64; idx += 256) {
        int r = idx >> 6, c = (idx & 63) * 2;
        float2 vw = *reinterpret_cast<const float2*>(Wl + r * 128 + c);
        cvt_store_pair_B(sm, r, c, vw);
        int row = rowBase + r;
        float2 va = make_float2(0.f, 0.f);
        if (row < NN) {
            va = *reinterpret_cast<const float2*>(g_agg + (size_t)row * DD + c);
            float inv = invs[r];
            va.x *= inv; va.y *= inv;
        }
        cvt_store_pair(sm, r, c, va);
    }
    __syncthreads();

    float acc[2][8][4];
    #pragma unroll
    for (int i = 0; i < 2; i++)
        #pragma unroll
        for (int j = 0; j < 8; j++)
            #pragma unroll
            for (int q = 0; q < 4; q++) acc[i][j][q] = 0.f;

    mma_tile(sb, acc, wr, wc, l);
    __syncthreads();

    // phase 2 tiles: B = Wr, A = H
    for (int idx = tid; idx < 128 * 64; idx += 256) {
        int r = idx >> 6, c = (idx & 63) * 2;
        float2 vw = *reinterpret_cast<const float2*>(Wr + r * 128 + c);
        cvt_store_pair_B(sm, r, c, vw);
        int row = rowBase + r;
        float2 va = make_float2(0.f, 0.f);
        if (row < NN) va = *reinterpret_cast<const float2*>(H + (size_t)row * DD + c);
        cvt_store_pair(sm, r, c, va);
    }
    __syncthreads();

    mma_tile(sb, acc, wr, wc, l);
    epilogue(acc, bl, Y, rowBase, wr, wc, l);
}

// ===========================================================================
extern "C" void kernel_launch(void* const* d_in, const int* in_sizes, int n_in,
                              void* d_out, int out_size) {
    const float* x     = (const float*)d_in[0];
    const void*  ei    = d_in[1];
    const float* W1    = (const float*)d_in[2];
    const float* b1    = (const float*)d_in[3];
    const float* W2    = (const float*)d_in[4];
    const float* b2    = (const float*)d_in[5];
    const float* c1_Wl = (const float*)d_in[6];
    const float* c1_bl = (const float*)d_in[7];
    const float* c1_Wr = (const float*)d_in[8];
    const float* c2_Wl = (const float*)d_in[9];
    const float* c2_bl = (const float*)d_in[10];
    const float* c2_Wr = (const float*)d_in[11];
    float* out = (float*)d_out;

    cudaFuncSetAttribute(gemm_lin_kernel,
                         cudaFuncAttributeMaxDynamicSharedMemorySize, GEMM_SMEM);
    cudaFuncSetAttribute(gemm_sage_kernel,
                         cudaFuncAttributeMaxDynamicSharedMemorySize, COMB_SMEM);

    float *p_h, *p_h2;
    cudaGetSymbolAddress((void**)&p_h, g_h);
    cudaGetSymbolAddress((void**)&p_h2, g_h2);

    int nb = (NN + 127) / 128;                    // 782 tiles
    int scatter_blocks = (EE * 32 + 255) / 256;   // one warp per edge
    int conv_blocks = (EE + 255) / 256;

    // edge preprocessing
    detect_kernel<<<1, 32>>>((const long long*)ei);
    zero_deg_kernel<<<(NN + 255) / 256, 256>>>();
    convert_kernel<<<conv_blocks, 256>>>(ei);

    // layer 1
    gemm_lin_kernel<<<nb, 256, GEMM_SMEM>>>(x, W1, b1, p_h);
    // sage 1
    zero_agg_kernel<<<1024, 256>>>();
    scatter_kernel<<<scatter_blocks, 256>>>(p_h);
    gemm_sage_kernel<<<nb, 256, COMB_SMEM>>>(p_h, c1_Wl, c1_bl, c1_Wr, p_h2);
    // layer 2
    gemm_lin_kernel<<<nb, 256, GEMM_SMEM>>>(p_h2, W2, b2, p_h);
    // sage 2 -> out
    zero_agg_kernel<<<1024, 256>>>();
    scatter_kernel<<<scatter_blocks, 256>>>(p_h);
    gemm_sage_kernel<<<nb, 256, COMB_SMEM>>>(p_h, c2_Wl, c2_bl, c2_Wr, out);
}

// round 8
// speedup vs baseline: 2.1136x; 1.1789x over previous
#include <cuda_runtime.h>
#include <cuda_bf16.h>
#include <cstdint>

#define NN 100000
#define EE 1600000
#define DD 128

// Scratch (allocation-free rule: __device__ globals)
__device__ float g_h   [NN * DD];
__device__ float g_h2  [NN * DD];
__device__ float g_agg [NN * DD];
__device__ int   g_src [EE];
__device__ int   g_dst [EE];
__device__ int   g_esrc[EE];
__device__ int   g_degi[NN];
__device__ int   g_rowptr[NN + 1];
__device__ int   g_cursor[NN];
__device__ int   g_is64;

// ===========================================================================
// PTX helpers (sm_80-compatible only: ldmatrix + mma.sync; NO tcgen05 — the
// harness compiles PTX at target compute_103, which rejects 'a' features)
// ===========================================================================
__device__ __forceinline__ uint32_t smem_u32(const void* p) {
    uint32_t a;
    asm("{ .reg .u64 t; cvta.to.shared.u64 t, %1; cvt.u32.u64 %0, t; }"
        : "=r"(a) : "l"(p));
    return a;
}
__device__ __forceinline__ void ldsm_x4(uint32_t* r, uint32_t addr) {
    asm volatile("ldmatrix.sync.aligned.m8n8.x4.shared.b16 {%0,%1,%2,%3}, [%4];"
                 : "=r"(r[0]), "=r"(r[1]), "=r"(r[2]), "=r"(r[3]) : "r"(addr));
}
__device__ __forceinline__ void mma16816(float* d, const uint32_t* a,
                                         const uint32_t* b) {
    asm volatile(
        "mma.sync.aligned.m16n8k16.row.col.f32.bf16.bf16.f32 "
        "{%0,%1,%2,%3}, {%4,%5,%6,%7}, {%8,%9}, {%0,%1,%2,%3};"
        : "+f"(d[0]), "+f"(d[1]), "+f"(d[2]), "+f"(d[3])
        : "r"(a[0]), "r"(a[1]), "r"(a[2]), "r"(a[3]), "r"(b[0]), "r"(b[1]));
}

// ===========================================================================
// Smem tile layout: bf16 [128][BSTRIDE], BSTRIDE=136.
// Regions: A_hi, A_lo, B_hi, B_lo (B = weight, K-major = W row-major).
// ===========================================================================
#define BSTRIDE 136
#define TILE_B  (128 * BSTRIDE * 2)   // 34816 bytes
#define R_A_HI  0
#define R_A_LO  (TILE_B)
#define R_B_HI  (2 * TILE_B)
#define R_B_LO  (3 * TILE_B)
#define GEMM_SMEM (4 * TILE_B)        // 139264

// split fp32 pair -> bf16 hi/lo
__device__ __forceinline__ void cvt_store_pair(char* sm, int r, int c, float2 v) {
    __nv_bfloat16 h0 = __float2bfloat16(v.x);
    __nv_bfloat16 h1 = __float2bfloat16(v.y);
    __nv_bfloat16 l0 = __float2bfloat16(v.x - __bfloat162float(h0));
    __nv_bfloat16 l1 = __float2bfloat16(v.y - __bfloat162float(h1));
    uint32_t off = (uint32_t)(r * BSTRIDE + c) * 2;
    *reinterpret_cast<__nv_bfloat162*>(sm + R_A_HI + off) = __halves2bfloat162(h0, h1);
    *reinterpret_cast<__nv_bfloat162*>(sm + R_A_LO + off) = __halves2bfloat162(l0, l1);
}
__device__ __forceinline__ void cvt_store_pair_B(char* sm, int r, int c, float2 v) {
    __nv_bfloat16 h0 = __float2bfloat16(v.x);
    __nv_bfloat16 h1 = __float2bfloat16(v.y);
    __nv_bfloat16 l0 = __float2bfloat16(v.x - __bfloat162float(h0));
    __nv_bfloat16 l1 = __float2bfloat16(v.y - __bfloat162float(h1));
    uint32_t off = (uint32_t)(r * BSTRIDE + c) * 2;
    *reinterpret_cast<__nv_bfloat162*>(sm + R_B_HI + off) = __halves2bfloat162(h0, h1);
    *reinterpret_cast<__nv_bfloat162*>(sm + R_B_LO + off) = __halves2bfloat162(l0, l1);
}

// Mainloop: warp tile 32x64 (wr 0..3, wc 0..1), 3-term split, accumulate.
// B loaded via ldsm.x4 covering n16 x k16 per issue (4 pairs per k-step).
__device__ __forceinline__ void mma_tile(uint32_t sb, float acc[2][8][4],
                                         int wr, int wc, int l) {
    #pragma unroll 2
    for (int k = 0; k < 8; k++) {
        uint32_t ah0[4], ah1[4], al0[4], al1[4];
        uint32_t arow0 = (uint32_t)(wr * 32 + (l & 15));
        uint32_t acolk = (uint32_t)(k * 16 + (l >> 4) * 8);
        uint32_t aoff0 = (arow0 * BSTRIDE + acolk) * 2;
        uint32_t aoff1 = ((arow0 + 16) * BSTRIDE + acolk) * 2;
        ldsm_x4(ah0, sb + R_A_HI + aoff0);
        ldsm_x4(ah1, sb + R_A_HI + aoff1);
        ldsm_x4(al0, sb + R_A_LO + aoff0);
        ldsm_x4(al1, sb + R_A_LO + aoff1);
        #pragma unroll
        for (int nfp = 0; nfp < 4; nfp++) {
            uint32_t bh4[4], bl4[4];
            // lanes 0-7: nf=2*nfp klo; 8-15: khi; 16-23: nf=2*nfp+1 klo; 24-31: khi
            uint32_t brow = (uint32_t)(wc * 64 + nfp * 16 + ((l >> 4) & 1) * 8 + (l & 7));
            uint32_t bcol = (uint32_t)(k * 16 + ((l >> 3) & 1) * 8);
            uint32_t boff = (brow * BSTRIDE + bcol) * 2;
            ldsm_x4(bh4, sb + R_B_HI + boff);
            ldsm_x4(bl4, sb + R_B_LO + boff);
            int nf0 = nfp * 2, nf1 = nfp * 2 + 1;
            mma16816(acc[0][nf0], ah0, bh4 + 0);
            mma16816(acc[1][nf0], ah1, bh4 + 0);
            mma16816(acc[0][nf1], ah0, bh4 + 2);
            mma16816(acc[1][nf1], ah1, bh4 + 2);
            mma16816(acc[0][nf0], ah0, bl4 + 0);
            mma16816(acc[1][nf0], ah1, bl4 + 0);
            mma16816(acc[0][nf1], ah0, bl4 + 2);
            mma16816(acc[1][nf1], ah1, bl4 + 2);
            mma16816(acc[0][nf0], al0, bh4 + 0);
            mma16816(acc[1][nf0], al1, bh4 + 0);
            mma16816(acc[0][nf1], al0, bh4 + 2);
            mma16816(acc[1][nf1], al1, bh4 + 2);
        }
    }
}

__device__ __forceinline__ void epilogue(float acc[2][8][4], const float* bias,
                                         float* Y, int rowBase, int wr, int wc,
                                         int l) {
    #pragma unroll
    for (int mf = 0; mf < 2; mf++) {
        #pragma unroll
        for (int nf = 0; nf < 8; nf++) {
            int col = wc * 64 + nf * 8 + (l & 3) * 2;
            float b0 = __ldg(bias + col), b1 = __ldg(bias + col + 1);
            int row0 = rowBase + wr * 32 + mf * 16 + (l >> 2);
            if (row0 < NN) {
                float2 v;
                v.x = fmaxf(acc[mf][nf][0] + b0, 0.f);
                v.y = fmaxf(acc[mf][nf][1] + b1, 0.f);
                *reinterpret_cast<float2*>(Y + (size_t)row0 * DD + col) = v;
            }
            int row1 = row0 + 8;
            if (row1 < NN) {
                float2 v;
                v.x = fmaxf(acc[mf][nf][2] + b0, 0.f);
                v.y = fmaxf(acc[mf][nf][3] + b1, 0.f);
                *reinterpret_cast<float2*>(Y + (size_t)row1 * DD + col) = v;
            }
        }
    }
}

// ===========================================================================
// Edge preprocessing: dtype detect, int32 edge lists, CSR build
// ===========================================================================
__global__ void detect_kernel(const long long* __restrict__ ei) {
    if (blockIdx.x == 0 && threadIdx.x == 0) {
        int ok = 1;
        #pragma unroll
        for (int i = 0; i < 16; i++) {
            long long v = ei[(size_t)i * (EE / 16) + 3];
            if (v < 0 || v >= NN) ok = 0;
        }
        g_is64 = ok;
    }
}

__global__ void zero_degi_kernel() {
    int i = blockIdx.x * blockDim.x + threadIdx.x;
    if (i < NN) g_degi[i] = 0;
}

__global__ void convert_kernel(const void* __restrict__ ei_raw) {
    int e = blockIdx.x * blockDim.x + threadIdx.x;
    if (e >= EE) return;
    int s, d;
    if (g_is64) {
        const long long* ei = (const long long*)ei_raw;
        s = (int)ei[e];
        d = (int)ei[EE + e];
    } else {
        const int* ei = (const int*)ei_raw;
        s = ei[e];
        d = ei[EE + e];
    }
    g_src[e] = s;
    g_dst[e] = d;
    atomicAdd(&g_degi[d], 1);
}

// Single-block exclusive scan over g_degi -> g_rowptr / g_cursor
#define SCAN_T 1024
__global__ void scan_kernel() {
    __shared__ int ss[SCAN_T];
    int t = threadIdx.x;
    const int C = (NN + SCAN_T - 1) / SCAN_T;   // 98
    int lo = t * C, hi = min(lo + C, NN);
    int s = 0;
    for (int i = lo; i < hi; i++) s += g_degi[i];
    ss[t] = s;
    __syncthreads();
    // Hillis-Steele inclusive scan
    for (int d = 1; d < SCAN_T; d <<= 1) {
        int v = (t >= d) ? ss[t - d] : 0;
        __syncthreads();
        ss[t] += v;
        __syncthreads();
    }
    int off = (t > 0) ? ss[t - 1] : 0;
    for (int i = lo; i < hi; i++) {
        g_rowptr[i] = off;
        g_cursor[i] = off;
        off += g_degi[i];
    }
    if (t == SCAN_T - 1) g_rowptr[NN] = off;
}

__global__ void bucket_kernel() {
    int e = blockIdx.x * blockDim.x + threadIdx.x;
    if (e >= EE) return;
    int pos = atomicAdd(&g_cursor[g_dst[e]], 1);
    g_esrc[pos] = g_src[e];
}

// ===========================================================================
// Mean aggregation: warp per dst node, gather over CSR, write mean.
// ===========================================================================
__global__ void gather_mean_kernel(const float* __restrict__ H) {
    int w = (blockIdx.x * blockDim.x + threadIdx.x) >> 5;
    int lane = threadIdx.x & 31;
    if (w >= NN) return;
    int beg = g_rowptr[w], end = g_rowptr[w + 1];
    float4 acc = make_float4(0.f, 0.f, 0.f, 0.f);
    for (int base = beg; base < end; base += 32) {
        int cnt = min(32, end - base);
        int s = (lane < cnt) ? g_esrc[base + lane] : 0;
        for (int j = 0; j < cnt; j++) {
            int sj = __shfl_sync(0xFFFFFFFF, s, j);
            float4 v = reinterpret_cast<const float4*>(H + (size_t)sj * DD)[lane];
            acc.x += v.x; acc.y += v.y; acc.z += v.z; acc.w += v.w;
        }
    }
    float inv = (end > beg) ? 1.0f / (float)(end - beg) : 0.0f;
    acc.x *= inv; acc.y *= inv; acc.z *= inv; acc.w *= inv;
    reinterpret_cast<float4*>(g_agg + (size_t)w * DD)[lane] = acc;
}

// ===========================================================================
// GEMM 1: Y = relu(X @ W^T + b)
// ===========================================================================
__global__ __launch_bounds__(256, 1)
void gemm_lin_kernel(const float* __restrict__ X, const float* __restrict__ W,
                     const float* __restrict__ b, float* __restrict__ Y) {
    extern __shared__ char sm[];
    uint32_t sb = smem_u32(sm);
    int tid = threadIdx.x, wid = tid >> 5, l = tid & 31;
    int wr = wid >> 1, wc = wid & 1;
    int rowBase = blockIdx.x * 128;

    for (int idx = tid; idx < 128 * 64; idx += 256) {
        int r = idx >> 6, c = (idx & 63) * 2;
        float2 vw = *reinterpret_cast<const float2*>(W + r * 128 + c);
        cvt_store_pair_B(sm, r, c, vw);
        int row = rowBase + r;
        float2 vx = make_float2(0.f, 0.f);
        if (row < NN) vx = *reinterpret_cast<const float2*>(X + (size_t)row * DD + c);
        cvt_store_pair(sm, r, c, vx);
    }
    __syncthreads();

    float acc[2][8][4];
    #pragma unroll
    for (int i = 0; i < 2; i++)
        #pragma unroll
        for (int j = 0; j < 8; j++)
            #pragma unroll
            for (int q = 0; q < 4; q++) acc[i][j][q] = 0.f;

    mma_tile(sb, acc, wr, wc, l);
    epilogue(acc, b, Y, rowBase, wr, wc, l);
}

// ===========================================================================
// GEMM 2: Y = relu( mean @ Wl^T + bl + H @ Wr^T ), two phases, reg accum
// (g_agg already holds the mean)
// ===========================================================================
__global__ __launch_bounds__(256, 1)
void gemm_sage_kernel(const float* __restrict__ H, const float* __restrict__ Wl,
                      const float* __restrict__ bl, const float* __restrict__ Wr,
                      float* __restrict__ Y) {
    extern __shared__ char sm[];
    uint32_t sb = smem_u32(sm);
    int tid = threadIdx.x, wid = tid >> 5, l = tid & 31;
    int wr = wid >> 1, wc = wid & 1;
    int rowBase = blockIdx.x * 128;

    // phase 1 tiles: B = Wl, A = mean
    for (int idx = tid; idx < 128 * 64; idx += 256) {
        int r = idx >> 6, c = (idx & 63) * 2;
        float2 vw = *reinterpret_cast<const float2*>(Wl + r * 128 + c);
        cvt_store_pair_B(sm, r, c, vw);
        int row = rowBase + r;
        float2 va = make_float2(0.f, 0.f);
        if (row < NN) va = *reinterpret_cast<const float2*>(g_agg + (size_t)row * DD + c);
        cvt_store_pair(sm, r, c, va);
    }
    __syncthreads();

    float acc[2][8][4];
    #pragma unroll
    for (int i = 0; i < 2; i++)
        #pragma unroll
        for (int j = 0; j < 8; j++)
            #pragma unroll
            for (int q = 0; q < 4; q++) acc[i][j][q] = 0.f;

    mma_tile(sb, acc, wr, wc, l);
    __syncthreads();

    // phase 2 tiles: B = Wr, A = H
    for (int idx = tid; idx < 128 * 64; idx += 256) {
        int r = idx >> 6, c = (idx & 63) * 2;
        float2 vw = *reinterpret_cast<const float2*>(Wr + r * 128 + c);
        cvt_store_pair_B(sm, r, c, vw);
        int row = rowBase + r;
        float2 va = make_float2(0.f, 0.f);
        if (row < NN) va = *reinterpret_cast<const float2*>(H + (size_t)row * DD + c);
        cvt_store_pair(sm, r, c, va);
    }
    __syncthreads();

    mma_tile(sb, acc, wr, wc, l);
    epilogue(acc, bl, Y, rowBase, wr, wc, l);
}

// ===========================================================================
extern "C" void kernel_launch(void* const* d_in, const int* in_sizes, int n_in,
                              void* d_out, int out_size) {
    const float* x     = (const float*)d_in[0];
    const void*  ei    = d_in[1];
    const float* W1    = (const float*)d_in[2];
    const float* b1    = (const float*)d_in[3];
    const float* W2    = (const float*)d_in[4];
    const float* b2    = (const float*)d_in[5];
    const float* c1_Wl = (const float*)d_in[6];
    const float* c1_bl = (const float*)d_in[7];
    const float* c1_Wr = (const float*)d_in[8];
    const float* c2_Wl = (const float*)d_in[9];
    const float* c2_bl = (const float*)d_in[10];
    const float* c2_Wr = (const float*)d_in[11];
    float* out = (float*)d_out;

    cudaFuncSetAttribute(gemm_lin_kernel,
                         cudaFuncAttributeMaxDynamicSharedMemorySize, GEMM_SMEM);
    cudaFuncSetAttribute(gemm_sage_kernel,
                         cudaFuncAttributeMaxDynamicSharedMemorySize, GEMM_SMEM);

    float *p_h, *p_h2;
    cudaGetSymbolAddress((void**)&p_h, g_h);
    cudaGetSymbolAddress((void**)&p_h2, g_h2);

    int nb = (NN + 127) / 128;                      // 782 tiles
    int conv_blocks = (EE + 255) / 256;
    int gather_blocks = (NN * 32 + 255) / 256;      // one warp per node

    // edge preprocessing + CSR build
    detect_kernel<<<1, 32>>>((const long long*)ei);
    zero_degi_kernel<<<(NN + 255) / 256, 256>>>();
    convert_kernel<<<conv_blocks, 256>>>(ei);
    scan_kernel<<<1, SCAN_T>>>();
    bucket_kernel<<<conv_blocks, 256>>>();

    // layer 1
    gemm_lin_kernel<<<nb, 256, GEMM_SMEM>>>(x, W1, b1, p_h);
    // sage 1
    gather_mean_kernel<<<gather_blocks, 256>>>(p_h);
    gemm_sage_kernel<<<nb, 256, GEMM_SMEM>>>(p_h, c1_Wl, c1_bl, c1_Wr, p_h2);
    // layer 2
    gemm_lin_kernel<<<nb, 256, GEMM_SMEM>>>(p_h2, W2, b2, p_h);
    // sage 2 -> out
    gather_mean_kernel<<<gather_blocks, 256>>>(p_h);
    gemm_sage_kernel<<<nb, 256, GEMM_SMEM>>>(p_h, c2_Wl, c2_bl, c2_Wr, out);
}

// round 9
// speedup vs baseline: 2.7191x; 1.2865x over previous
#include <cuda_runtime.h>
#include <cuda_bf16.h>
#include <cstdint>

#define NN 100000
#define EE 1600000
#define DD 128

// Scratch (allocation-free rule: __device__ globals)
__device__ float g_h   [NN * DD];
__device__ float g_h2  [NN * DD];
__device__ float g_agg [NN * DD];
__device__ int   g_src [EE];
__device__ int   g_dst [EE];
__device__ int   g_esrc[EE];
__device__ int   g_degi[NN];
__device__ int   g_rowptr[NN + 1];
__device__ int   g_cursor[NN];
__device__ int   g_bsum[128];
__device__ int   g_boff[128];
__device__ int   g_is64;

// ===========================================================================
// PTX helpers (sm_80-compatible only: ldmatrix + mma.sync; NO tcgen05 — the
// harness compiles PTX at target compute_103, which rejects 'a' features)
// ===========================================================================
__device__ __forceinline__ uint32_t smem_u32(const void* p) {
    uint32_t a;
    asm("{ .reg .u64 t; cvta.to.shared.u64 t, %1; cvt.u32.u64 %0, t; }"
        : "=r"(a) : "l"(p));
    return a;
}
__device__ __forceinline__ void ldsm_x4(uint32_t* r, uint32_t addr) {
    asm volatile("ldmatrix.sync.aligned.m8n8.x4.shared.b16 {%0,%1,%2,%3}, [%4];"
                 : "=r"(r[0]), "=r"(r[1]), "=r"(r[2]), "=r"(r[3]) : "r"(addr));
}
__device__ __forceinline__ void mma16816(float* d, const uint32_t* a,
                                         const uint32_t* b) {
    asm volatile(
        "mma.sync.aligned.m16n8k16.row.col.f32.bf16.bf16.f32 "
        "{%0,%1,%2,%3}, {%4,%5,%6,%7}, {%8,%9}, {%0,%1,%2,%3};"
        : "+f"(d[0]), "+f"(d[1]), "+f"(d[2]), "+f"(d[3])
        : "r"(a[0]), "r"(a[1]), "r"(a[2]), "r"(a[3]), "r"(b[0]), "r"(b[1]));
}

// ===========================================================================
// Smem tile layout: bf16 [128][BSTRIDE], BSTRIDE=136.
// Regions: A_hi, A_lo, B_hi, B_lo (B = weight, K-major = W row-major).
// ===========================================================================
#define BSTRIDE 136
#define TILE_B  (128 * BSTRIDE * 2)   // 34816 bytes
#define R_A_HI  0
#define R_A_LO  (TILE_B)
#define R_B_HI  (2 * TILE_B)
#define R_B_LO  (3 * TILE_B)
#define GEMM_SMEM (4 * TILE_B)        // 139264

// split fp32 pair -> bf16 hi/lo
__device__ __forceinline__ void cvt_store_pair(char* sm, int r, int c, float2 v) {
    __nv_bfloat16 h0 = __float2bfloat16(v.x);
    __nv_bfloat16 h1 = __float2bfloat16(v.y);
    __nv_bfloat16 l0 = __float2bfloat16(v.x - __bfloat162float(h0));
    __nv_bfloat16 l1 = __float2bfloat16(v.y - __bfloat162float(h1));
    uint32_t off = (uint32_t)(r * BSTRIDE + c) * 2;
    *reinterpret_cast<__nv_bfloat162*>(sm + R_A_HI + off) = __halves2bfloat162(h0, h1);
    *reinterpret_cast<__nv_bfloat162*>(sm + R_A_LO + off) = __halves2bfloat162(l0, l1);
}
__device__ __forceinline__ void cvt_store_pair_B(char* sm, int r, int c, float2 v) {
    __nv_bfloat16 h0 = __float2bfloat16(v.x);
    __nv_bfloat16 h1 = __float2bfloat16(v.y);
    __nv_bfloat16 l0 = __float2bfloat16(v.x - __bfloat162float(h0));
    __nv_bfloat16 l1 = __float2bfloat16(v.y - __bfloat162float(h1));
    uint32_t off = (uint32_t)(r * BSTRIDE + c) * 2;
    *reinterpret_cast<__nv_bfloat162*>(sm + R_B_HI + off) = __halves2bfloat162(h0, h1);
    *reinterpret_cast<__nv_bfloat162*>(sm + R_B_LO + off) = __halves2bfloat162(l0, l1);
}

// Mainloop: warp tile 32x64 (wr 0..3, wc 0..1), 3-term split, accumulate.
// B loaded via ldsm.x4 covering n16 x k16 per issue (4 pairs per k-step).
__device__ __forceinline__ void mma_tile(uint32_t sb, float acc[2][8][4],
                                         int wr, int wc, int l) {
    #pragma unroll 2
    for (int k = 0; k < 8; k++) {
        uint32_t ah0[4], ah1[4], al0[4], al1[4];
        uint32_t arow0 = (uint32_t)(wr * 32 + (l & 15));
        uint32_t acolk = (uint32_t)(k * 16 + (l >> 4) * 8);
        uint32_t aoff0 = (arow0 * BSTRIDE + acolk) * 2;
        uint32_t aoff1 = ((arow0 + 16) * BSTRIDE + acolk) * 2;
        ldsm_x4(ah0, sb + R_A_HI + aoff0);
        ldsm_x4(ah1, sb + R_A_HI + aoff1);
        ldsm_x4(al0, sb + R_A_LO + aoff0);
        ldsm_x4(al1, sb + R_A_LO + aoff1);
        #pragma unroll
        for (int nfp = 0; nfp < 4; nfp++) {
            uint32_t bh4[4], bl4[4];
            uint32_t brow = (uint32_t)(wc * 64 + nfp * 16 + ((l >> 4) & 1) * 8 + (l & 7));
            uint32_t bcol = (uint32_t)(k * 16 + ((l >> 3) & 1) * 8);
            uint32_t boff = (brow * BSTRIDE + bcol) * 2;
            ldsm_x4(bh4, sb + R_B_HI + boff);
            ldsm_x4(bl4, sb + R_B_LO + boff);
            int nf0 = nfp * 2, nf1 = nfp * 2 + 1;
            mma16816(acc[0][nf0], ah0, bh4 + 0);
            mma16816(acc[1][nf0], ah1, bh4 + 0);
            mma16816(acc[0][nf1], ah0, bh4 + 2);
            mma16816(acc[1][nf1], ah1, bh4 + 2);
            mma16816(acc[0][nf0], ah0, bl4 + 0);
            mma16816(acc[1][nf0], ah1, bl4 + 0);
            mma16816(acc[0][nf1], ah0, bl4 + 2);
            mma16816(acc[1][nf1], ah1, bl4 + 2);
            mma16816(acc[0][nf0], al0, bh4 + 0);
            mma16816(acc[1][nf0], al1, bh4 + 0);
            mma16816(acc[0][nf1], al0, bh4 + 2);
            mma16816(acc[1][nf1], al1, bh4 + 2);
        }
    }
}

__device__ __forceinline__ void epilogue(float acc[2][8][4], const float* bias,
                                         float* Y, int rowBase, int wr, int wc,
                                         int l) {
    #pragma unroll
    for (int mf = 0; mf < 2; mf++) {
        #pragma unroll
        for (int nf = 0; nf < 8; nf++) {
            int col = wc * 64 + nf * 8 + (l & 3) * 2;
            float b0 = __ldg(bias + col), b1 = __ldg(bias + col + 1);
            int row0 = rowBase + wr * 32 + mf * 16 + (l >> 2);
            if (row0 < NN) {
                float2 v;
                v.x = fmaxf(acc[mf][nf][0] + b0, 0.f);
                v.y = fmaxf(acc[mf][nf][1] + b1, 0.f);
                *reinterpret_cast<float2*>(Y + (size_t)row0 * DD + col) = v;
            }
            int row1 = row0 + 8;
            if (row1 < NN) {
                float2 v;
                v.x = fmaxf(acc[mf][nf][2] + b0, 0.f);
                v.y = fmaxf(acc[mf][nf][3] + b1, 0.f);
                *reinterpret_cast<float2*>(Y + (size_t)row1 * DD + col) = v;
            }
        }
    }
}

// ===========================================================================
// Edge preprocessing: dtype detect, int32 edge lists, CSR build
// ===========================================================================
__global__ void detect_kernel(const long long* __restrict__ ei) {
    int t = threadIdx.x;
    long long v = ei[(size_t)(t & 15) * (EE / 16) + 3];
    unsigned bad = __ballot_sync(0xFFFFFFFF, v < 0 || v >= NN);
    if (t == 0) g_is64 = (bad == 0) ? 1 : 0;
}

__global__ void zero_degi_kernel() {
    int i = blockIdx.x * blockDim.x + threadIdx.x;
    if (i < NN) g_degi[i] = 0;
}

__global__ void convert_kernel(const void* __restrict__ ei_raw) {
    int e = blockIdx.x * blockDim.x + threadIdx.x;
    if (e >= EE) return;
    int s, d;
    if (g_is64) {
        const long long* ei = (const long long*)ei_raw;
        s = (int)ei[e];
        d = (int)ei[EE + e];
    } else {
        const int* ei = (const int*)ei_raw;
        s = ei[e];
        d = ei[EE + e];
    }
    g_src[e] = s;
    g_dst[e] = d;
    atomicAdd(&g_degi[d], 1);
}

// --- 3-phase parallel exclusive scan over g_degi -> g_rowptr / g_cursor ---
#define SCAN_BT 1024
#define SCAN_NB ((NN + SCAN_BT - 1) / SCAN_BT)   // 98

__global__ void scan_block_kernel() {
    __shared__ int ss[SCAN_BT];
    int t = threadIdx.x;
    int i = blockIdx.x * SCAN_BT + t;
    int v = (i < NN) ? g_degi[i] : 0;
    ss[t] = v;
    __syncthreads();
    for (int d = 1; d < SCAN_BT; d <<= 1) {
        int u = (t >= d) ? ss[t - d] : 0;
        __syncthreads();
        ss[t] += u;
        __syncthreads();
    }
    if (i < NN) g_rowptr[i] = ss[t] - v;   // exclusive within block
    if (t == SCAN_BT - 1) g_bsum[blockIdx.x] = ss[t];
}

__global__ void scan_bsum_kernel() {
    __shared__ int ss[128];
    int t = threadIdx.x;
    int v = (t < SCAN_NB) ? g_bsum[t] : 0;
    ss[t] = v;
    __syncthreads();
    for (int d = 1; d < 128; d <<= 1) {
        int u = (t >= d) ? ss[t - d] : 0;
        __syncthreads();
        ss[t] += u;
        __syncthreads();
    }
    g_boff[t] = ss[t] - v;   // exclusive
}

__global__ void scan_apply_kernel() {
    int i = blockIdx.x * SCAN_BT + threadIdx.x;
    if (i < NN) {
        int val = g_rowptr[i] + g_boff[blockIdx.x];
        g_rowptr[i] = val;
        g_cursor[i] = val;
    }
    if (i == 0) g_rowptr[NN] = EE;
}

__global__ void bucket_kernel() {
    int e = blockIdx.x * blockDim.x + threadIdx.x;
    if (e >= EE) return;
    int pos = atomicAdd(&g_cursor[g_dst[e]], 1);
    g_esrc[pos] = g_src[e];
}

// ===========================================================================
// Mean aggregation: warp per dst node, gather over CSR, write mean.
// ===========================================================================
__global__ void gather_mean_kernel(const float* __restrict__ H) {
    int w = (blockIdx.x * blockDim.x + threadIdx.x) >> 5;
    int lane = threadIdx.x & 31;
    if (w >= NN) return;
    int beg = g_rowptr[w], end = g_rowptr[w + 1];
    float4 acc = make_float4(0.f, 0.f, 0.f, 0.f);
    for (int base = beg; base < end; base += 32) {
        int cnt = min(32, end - base);
        int s = (lane < cnt) ? g_esrc[base + lane] : 0;
        for (int j = 0; j < cnt; j++) {
            int sj = __shfl_sync(0xFFFFFFFF, s, j);
            float4 v = reinterpret_cast<const float4*>(H + (size_t)sj * DD)[lane];
            acc.x += v.x; acc.y += v.y; acc.z += v.z; acc.w += v.w;
        }
    }
    float inv = (end > beg) ? 1.0f / (float)(end - beg) : 0.0f;
    acc.x *= inv; acc.y *= inv; acc.z *= inv; acc.w *= inv;
    reinterpret_cast<float4*>(g_agg + (size_t)w * DD)[lane] = acc;
}

// ===========================================================================
// GEMM 1: Y = relu(X @ W^T + b)
// ===========================================================================
__global__ __launch_bounds__(256, 1)
void gemm_lin_kernel(const float* __restrict__ X, const float* __restrict__ W,
                     const float* __restrict__ b, float* __restrict__ Y) {
    extern __shared__ char sm[];
    uint32_t sb = smem_u32(sm);
    int tid = threadIdx.x, wid = tid >> 5, l = tid & 31;
    int wr = wid >> 1, wc = wid & 1;
    int rowBase = blockIdx.x * 128;

    for (int idx = tid; idx < 128 * 64; idx += 256) {
        int r = idx >> 6, c = (idx & 63) * 2;
        float2 vw = *reinterpret_cast<const float2*>(W + r * 128 + c);
        cvt_store_pair_B(sm, r, c, vw);
        int row = rowBase + r;
        float2 vx = make_float2(0.f, 0.f);
        if (row < NN) vx = *reinterpret_cast<const float2*>(X + (size_t)row * DD + c);
        cvt_store_pair(sm, r, c, vx);
    }
    __syncthreads();

    float acc[2][8][4];
    #pragma unroll
    for (int i = 0; i < 2; i++)
        #pragma unroll
        for (int j = 0; j < 8; j++)
            #pragma unroll
            for (int q = 0; q < 4; q++) acc[i][j][q] = 0.f;

    mma_tile(sb, acc, wr, wc, l);
    epilogue(acc, b, Y, rowBase, wr, wc, l);
}

// ===========================================================================
// GEMM 2: Y = relu( mean @ Wl^T + bl + H @ Wr^T ), two phases, reg accum
// (g_agg already holds the mean)
// ===========================================================================
__global__ __launch_bounds__(256, 1)
void gemm_sage_kernel(const float* __restrict__ H, const float* __restrict__ Wl,
                      const float* __restrict__ bl, const float* __restrict__ Wr,
                      float* __restrict__ Y) {
    extern __shared__ char sm[];
    uint32_t sb = smem_u32(sm);
    int tid = threadIdx.x, wid = tid >> 5, l = tid & 31;
    int wr = wid >> 1, wc = wid & 1;
    int rowBase = blockIdx.x * 128;

    // phase 1 tiles: B = Wl, A = mean
    for (int idx = tid; idx < 128 * 64; idx += 256) {
        int r = idx >> 6, c = (idx & 63) * 2;
        float2 vw = *reinterpret_cast<const float2*>(Wl + r * 128 + c);
        cvt_store_pair_B(sm, r, c, vw);
        int row = rowBase + r;
        float2 va = make_float2(0.f, 0.f);
        if (row < NN) va = *reinterpret_cast<const float2*>(g_agg + (size_t)row * DD + c);
        cvt_store_pair(sm, r, c, va);
    }
    __syncthreads();

    float acc[2][8][4];
    #pragma unroll
    for (int i = 0; i < 2; i++)
        #pragma unroll
        for (int j = 0; j < 8; j++)
            #pragma unroll
            for (int q = 0; q < 4; q++) acc[i][j][q] = 0.f;

    mma_tile(sb, acc, wr, wc, l);
    __syncthreads();

    // phase 2 tiles: B = Wr, A = H
    for (int idx = tid; idx < 128 * 64; idx += 256) {
        int r = idx >> 6, c = (idx & 63) * 2;
        float2 vw = *reinterpret_cast<const float2*>(Wr + r * 128 + c);
        cvt_store_pair_B(sm, r, c, vw);
        int row = rowBase + r;
        float2 va = make_float2(0.f, 0.f);
        if (row < NN) va = *reinterpret_cast<const float2*>(H + (size_t)row * DD + c);
        cvt_store_pair(sm, r, c, va);
    }
    __syncthreads();

    mma_tile(sb, acc, wr, wc, l);
    epilogue(acc, bl, Y, rowBase, wr, wc, l);
}

// ===========================================================================
extern "C" void kernel_launch(void* const* d_in, const int* in_sizes, int n_in,
                              void* d_out, int out_size) {
    const float* x     = (const float*)d_in[0];
    const void*  ei    = d_in[1];
    const float* W1    = (const float*)d_in[2];
    const float* b1    = (const float*)d_in[3];
    const float* W2    = (const float*)d_in[4];
    const float* b2    = (const float*)d_in[5];
    const float* c1_Wl = (const float*)d_in[6];
    const float* c1_bl = (const float*)d_in[7];
    const float* c1_Wr = (const float*)d_in[8];
    const float* c2_Wl = (const float*)d_in[9];
    const float* c2_bl = (const float*)d_in[10];
    const float* c2_Wr = (const float*)d_in[11];
    float* out = (float*)d_out;

    cudaFuncSetAttribute(gemm_lin_kernel,
                         cudaFuncAttributeMaxDynamicSharedMemorySize, GEMM_SMEM);
    cudaFuncSetAttribute(gemm_sage_kernel,
                         cudaFuncAttributeMaxDynamicSharedMemorySize, GEMM_SMEM);

    float *p_h, *p_h2;
    cudaGetSymbolAddress((void**)&p_h, g_h);
    cudaGetSymbolAddress((void**)&p_h2, g_h2);

    int nb = (NN + 127) / 128;                      // 782 tiles
    int conv_blocks = (EE + 255) / 256;
    int gather_blocks = (NN * 32 + 255) / 256;      // one warp per node

    // edge preprocessing + CSR build
    detect_kernel<<<1, 32>>>((const long long*)ei);
    zero_degi_kernel<<<(NN + 255) / 256, 256>>>();
    convert_kernel<<<conv_blocks, 256>>>(ei);
    scan_block_kernel<<<SCAN_NB, SCAN_BT>>>();
    scan_bsum_kernel<<<1, 128>>>();
    scan_apply_kernel<<<SCAN_NB, SCAN_BT>>>();
    bucket_kernel<<<conv_blocks, 256>>>();

    // layer 1
    gemm_lin_kernel<<<nb, 256, GEMM_SMEM>>>(x, W1, b1, p_h);
    // sage 1
    gather_mean_kernel<<<gather_blocks, 256>>>(p_h);
    gemm_sage_kernel<<<nb, 256, GEMM_SMEM>>>(p_h, c1_Wl, c1_bl, c1_Wr, p_h2);
    // layer 2
    gemm_lin_kernel<<<nb, 256, GEMM_SMEM>>>(p_h2, W2, b2, p_h);
    // sage 2 -> out
    gather_mean_kernel<<<gather_blocks, 256>>>(p_h);
    gemm_sage_kernel<<<nb, 256, GEMM_SMEM>>>(p_h, c2_Wl, c2_bl, c2_Wr, out);
}